// round 4
// baseline (speedup 1.0000x reference)
#include <cuda_runtime.h>
#include <math.h>

// Problem constants
#define LEV     60
#define BATCH   4096
#define NXI     4
#define NH      64
#define NMEM    64
#define NSFC    17
#define NYO     4
#define XW1     68          // NXI + NMEM
#define KDIM    132         // unified K (rnn1: 68+64, rnn2: 64+64 zero-padded to 132)
#define NG      256         // 4*NH gate columns
#define NWCOL   320         // gates (256) + logvar (64)
#define TB      32          // batch rows per block
#define NTHREADS 512
#define NBLOCKS (BATCH / TB)   // 128

// shared layout (floats): W_s[NWCOL][KDIM] | xh0[TB][KDIM] | xh1[TB][KDIM] | lat[TB][NH] | wout | bout
#define SM_W     (NWCOL * KDIM)            // 42240
#define SM_XH    (TB * KDIM)               // 4224
#define SM_LAT   (TB * NH)                 // 2048
#define SMEM_FLOATS (SM_W + 2 * SM_XH + SM_LAT + NH * NYO + NYO)
#define SMEM_BYTES  (SMEM_FLOATS * 4)      // ~212KB < 232448 opt-in limit

// output layout: out (B,L,NYO) || out_sfc (B,3) || new_mem (B,L,NMEM)
#define OFF_OUT  0
#define OFF_SFC  (BATCH * LEV * NYO)                 // 983040
#define OFF_MEM  (OFF_SFC + BATCH * 3)               // 995328

// inter-phase scratch: rnn1out then (overwritten in place) rnn2out, [level][batch][NH]
__device__ float g_scratch[LEV * BATCH * NH];

struct Params {
    const float *inputs_main, *inputs_aux, *rnn1_mem, *eps1, *eps2, *eps_sfc;
    const float *W_sfc, *b_sfc, *W_sfc2, *b_sfc2, *W_toa, *b_toa, *W_toa2, *b_toa2;
    const float *Wx1, *Wh1, *Wxs1, *Whs1, *Wx2, *Wh2, *Wxs2, *Whs2;
    const float *W_lat, *b_lat, *W_out, *b_out, *W_sfcout, *b_sfcout;
    const float *W_mu, *b_mu, *W_lv, *b_lv;
    float *out;
};

__device__ __forceinline__ float sigmoidf_(float x) {
    return __fdividef(1.0f, 1.0f + __expf(-x));
}
__device__ __forceinline__ float tanhf_(float x) {
    float ax = fabsf(x);
    float e  = __expf(2.0f * ax);                    // overflow -> +inf -> term -> 0
    float t  = 1.0f - __fdividef(2.0f, e + 1.0f);
    return copysignf(t, x);
}

// packed fp32x2 FMA (Blackwell): d = a*b + c elementwise on {lo,hi}
__device__ __forceinline__ unsigned long long fma2_(unsigned long long a,
                                                    unsigned long long b,
                                                    unsigned long long c) {
    unsigned long long d;
    asm("fma.rn.f32x2 %0, %1, %2, %3;" : "=l"(d) : "l"(a), "l"(b), "l"(c));
    return d;
}
__device__ __forceinline__ float pairsum_(unsigned long long v) {
    float lo = __int_as_float((int)(v & 0xffffffffull));
    float hi = __int_as_float((int)(v >> 32));
    return lo + hi;
}

extern __shared__ float smem[];

__global__ __launch_bounds__(NTHREADS, 1)
void stochastic_rnn_kernel(Params p) {
    const int tid = threadIdx.x;
    const int b0  = blockIdx.x * TB;

    float* W_s  = smem;
    float* xhb[2] = { smem + SM_W, smem + SM_W + SM_XH };
    float* lat_s  = smem + SM_W + 2 * SM_XH;
    float* wout_s = lat_s + SM_LAT;
    float* bout_s = wout_s + NH * NYO;

    // thread identity: column tx (0..63), row group ty (0..7) -> rows ty*4+u
    const int tx = tid & 63;
    const int ty = tid >> 6;
    // x-staging identity: row r16 (0..31), quad q16 (0..15)
    const int r16 = tid >> 4;
    const int q16 = tid & 15;

    float c_reg[4];

    // ---------------- load rnn1 weights (transposed; coalesced reads) ----------------
    for (int idx = tid; idx < NWCOL * KDIM; idx += NTHREADS) {
        int k = idx / NWCOL, j = idx % NWCOL;     // consecutive threads -> consecutive j
        float v;
        if (j < NG) v = (k < XW1) ? p.Wx1[k * NG + j] : p.Wh1[(k - XW1) * NG + j];
        else {
            int jj = j - NG;
            v = (k < XW1) ? p.Wxs1[k * NH + jj] : p.Whs1[(k - XW1) * NH + jj];
        }
        W_s[j * KDIM + k] = v;
    }

    // ---------------- rnn1 initial h, c from surface MLPs ----------------
#pragma unroll
    for (int u = 0; u < 4; u++) {
        int row = ty * 4 + u;
        const float* auxrow = p.inputs_aux + (size_t)(b0 + row) * NSFC;
        float ah = p.b_sfc[tx], ac = p.b_sfc2[tx];
        for (int k = 0; k < NSFC; k++) {
            float a = auxrow[k];
            ah = fmaf(a, p.W_sfc[k * NH + tx], ah);
            ac = fmaf(a, p.W_sfc2[k * NH + tx], ac);
        }
        xhb[0][row * KDIM + XW1 + tx] = tanhf_(ah);
        c_reg[u] = tanhf_(ac);
    }

    // prefetch + commit x (level 59) into buffer 0
    float4 mr, xm;
    {
        size_t rowbase = ((size_t)(b0 + r16) * LEV + (LEV - 1));
        mr = *(const float4*)&p.rnn1_mem[rowbase * NMEM + q16 * 4];
        if (q16 == 0) xm = *(const float4*)&p.inputs_main[rowbase * NXI];
    }
    *(float4*)&xhb[0][r16 * KDIM + NXI + q16 * 4] = mr;
    if (q16 == 0) *(float4*)&xhb[0][r16 * KDIM] = xm;
    __syncthreads();

    // ---------------- rnn1: bottom-up, 1 sync/step, pointwise in registers ----------------
    for (int s = 0; s < LEV; s++) {
        int l = LEV - 1 - s;
        const float* cur = xhb[s & 1];
        float* nxt = xhb[(s + 1) & 1];

        // issue eps + next-x loads (latency hidden under the GEMM)
        float ge[4];
#pragma unroll
        for (int u = 0; u < 4; u++)
            ge[u] = p.eps1[((size_t)s * BATCH + b0 + ty * 4 + u) * NH + tx];
        if (s + 1 < LEV) {
            size_t rowbase = ((size_t)(b0 + r16) * LEV + (l - 1));
            mr = *(const float4*)&p.rnn1_mem[rowbase * NMEM + q16 * 4];
            if (q16 == 0) xm = *(const float4*)&p.inputs_main[rowbase * NXI];
        }

        // fused GEMM: acc[u][c] = gate c of (row ty*4+u, col tx)
        unsigned long long acc[4][5];
#pragma unroll
        for (int u = 0; u < 4; u++)
#pragma unroll
            for (int c = 0; c < 5; c++) acc[u][c] = 0ull;
#pragma unroll 1
        for (int kq = 0; kq < KDIM / 4; kq++) {
            ulonglong2 wv[5];
#pragma unroll
            for (int c = 0; c < 5; c++)
                wv[c] = *(const ulonglong2*)&W_s[(c * 64 + tx) * KDIM + kq * 4];
#pragma unroll
            for (int u = 0; u < 4; u++) {
                ulonglong2 xv = *(const ulonglong2*)&cur[(ty * 4 + u) * KDIM + kq * 4];
#pragma unroll
                for (int c = 0; c < 5; c++) {
                    acc[u][c] = fma2_(xv.x, wv[c].x, acc[u][c]);
                    acc[u][c] = fma2_(xv.y, wv[c].y, acc[u][c]);
                }
            }
        }

        // pointwise in registers
#pragma unroll
        for (int u = 0; u < 4; u++) {
            int row = ty * 4 + u;
            float gi = pairsum_(acc[u][0]);
            float gf = pairsum_(acc[u][1]);
            float gg = pairsum_(acc[u][2]);
            float go = pairsum_(acc[u][3]);
            float gv = pairsum_(acc[u][4]);
            float iv = sigmoidf_(gi);
            float fv = sigmoidf_(gf);
            float gt = tanhf_(gg);
            float ov = sigmoidf_(go);
            float c  = fv * c_reg[u] + iv * gt;
            c_reg[u] = c;
            float h  = ov * tanhf_(c) + ge[u] * __expf(0.5f * gv);
            nxt[row * KDIM + XW1 + tx] = h;
            g_scratch[((size_t)l * BATCH + b0 + row) * NH + tx] = h;
        }
        if (s + 1 < LEV) {
            *(float4*)&nxt[r16 * KDIM + NXI + q16 * 4] = mr;
            if (q16 == 0) *(float4*)&nxt[r16 * KDIM] = xm;
        }
        __syncthreads();
    }

    // ---------------- load rnn2 weights (K padded 128->132 with zeros) ----------------
    for (int idx = tid; idx < NWCOL * KDIM; idx += NTHREADS) {
        int k = idx / NWCOL, j = idx % NWCOL;
        float v = 0.0f;
        if (j < NG) {
            if (k < NH)            v = p.Wx2[k * NG + j];
            else if (k < 2 * NH)   v = p.Wh2[(k - NH) * NG + j];
        } else {
            int jj = j - NG;
            if (k < NH)            v = p.Wxs2[k * NH + jj];
            else if (k < 2 * NH)   v = p.Whs2[(k - NH) * NH + jj];
        }
        W_s[j * KDIM + k] = v;
    }
    // zero xh pad columns 128..131 in BOTH buffers (avoid 0*NaN)
    if (tid < 256) {
        int bsel = tid >> 7, r = (tid >> 2) & 31, kk = tid & 3;
        xhb[bsel][r * KDIM + 128 + kk] = 0.0f;
    }

    // rnn2 initial h, c from TOA MLPs (inputs_toa = aux[:,1], aux[:,6])
#pragma unroll
    for (int u = 0; u < 4; u++) {
        int row = ty * 4 + u;
        float x0 = p.inputs_aux[(size_t)(b0 + row) * NSFC + 1];
        float x1 = p.inputs_aux[(size_t)(b0 + row) * NSFC + 6];
        float ah = fmaf(x0, p.W_toa[tx],  fmaf(x1, p.W_toa[NH + tx],  p.b_toa[tx]));
        float ac = fmaf(x0, p.W_toa2[tx], fmaf(x1, p.W_toa2[NH + tx], p.b_toa2[tx]));
        xhb[0][row * KDIM + NH + tx] = tanhf_(ah);
        c_reg[u] = tanhf_(ac);
    }
    // prefetch + commit x (rnn1out level 0) into buffer 0
    float4 hr;
    hr = *(const float4*)&g_scratch[((size_t)0 * BATCH + b0 + r16) * NH + q16 * 4];
    *(float4*)&xhb[0][r16 * KDIM + q16 * 4] = hr;
    __syncthreads();

    // ---------------- rnn2: top-down; overwrite scratch in place ----------------
    for (int s = 0; s < LEV; s++) {
        const float* cur = xhb[s & 1];
        float* nxt = xhb[(s + 1) & 1];

        float ge[4];
#pragma unroll
        for (int u = 0; u < 4; u++)
            ge[u] = p.eps2[((size_t)s * BATCH + b0 + ty * 4 + u) * NH + tx];
        if (s + 1 < LEV)
            hr = *(const float4*)&g_scratch[((size_t)(s + 1) * BATCH + b0 + r16) * NH + q16 * 4];

        unsigned long long acc[4][5];
#pragma unroll
        for (int u = 0; u < 4; u++)
#pragma unroll
            for (int c = 0; c < 5; c++) acc[u][c] = 0ull;
#pragma unroll 1
        for (int kq = 0; kq < KDIM / 4; kq++) {
            ulonglong2 wv[5];
#pragma unroll
            for (int c = 0; c < 5; c++)
                wv[c] = *(const ulonglong2*)&W_s[(c * 64 + tx) * KDIM + kq * 4];
#pragma unroll
            for (int u = 0; u < 4; u++) {
                ulonglong2 xv = *(const ulonglong2*)&cur[(ty * 4 + u) * KDIM + kq * 4];
#pragma unroll
                for (int c = 0; c < 5; c++) {
                    acc[u][c] = fma2_(xv.x, wv[c].x, acc[u][c]);
                    acc[u][c] = fma2_(xv.y, wv[c].y, acc[u][c]);
                }
            }
        }

#pragma unroll
        for (int u = 0; u < 4; u++) {
            int row = ty * 4 + u;
            float gi = pairsum_(acc[u][0]);
            float gf = pairsum_(acc[u][1]);
            float gg = pairsum_(acc[u][2]);
            float go = pairsum_(acc[u][3]);
            float gv = pairsum_(acc[u][4]);
            float iv = sigmoidf_(gi);
            float fv = sigmoidf_(gf);
            float gt = tanhf_(gg);
            float ov = sigmoidf_(go);
            float c  = fv * c_reg[u] + iv * gt;
            c_reg[u] = c;
            float h  = ov * tanhf_(c) + ge[u] * __expf(0.5f * gv);
            nxt[row * KDIM + NH + tx] = h;
            g_scratch[((size_t)s * BATCH + b0 + row) * NH + tx] = h;
        }
        if (s + 1 < LEV)
            *(float4*)&nxt[r16 * KDIM + q16 * 4] = hr;
        __syncthreads();
    }

    float* hlast = xhb[0];   // h of step 59 landed in buffer (59+1)&1 = 0

    // ---------------- surface heads from last hidden (cols 64..127 of hlast) ----------------
    if (tid < TB) {
        int r = tid;
        size_t b = b0 + r;
        float rad = p.b_sfcout[0];
        float mu0 = p.b_mu[0], mu1 = p.b_mu[1];
        float lv0 = p.b_lv[0], lv1 = p.b_lv[1];
        for (int k = 0; k < NH; k++) {
            float h = hlast[r * KDIM + NH + k];
            rad = fmaf(h, p.W_sfcout[k], rad);
            mu0 = fmaf(h, p.W_mu[k * 2 + 0], mu0);
            mu1 = fmaf(h, p.W_mu[k * 2 + 1], mu1);
            lv0 = fmaf(h, p.W_lv[k * 2 + 0], lv0);
            lv1 = fmaf(h, p.W_lv[k * 2 + 1], lv1);
        }
        float e0 = p.eps_sfc[b * 2 + 0], e1 = p.eps_sfc[b * 2 + 1];
        p.out[OFF_SFC + b * 3 + 0] = mu0 + e0 * __expf(0.5f * lv0);
        p.out[OFF_SFC + b * 3 + 1] = mu1 + e1 * __expf(0.5f * lv1);
        p.out[OFF_SFC + b * 3 + 2] = rad;
    }

    // ---------------- load W_lat (transposed) + W_out/b_out ----------------
    for (int idx = tid; idx < NH * NH; idx += NTHREADS) {
        int k = idx >> 6, m = idx & 63;
        W_s[m * KDIM + k] = p.W_lat[idx];
    }
    for (int idx = tid; idx < NH * NYO; idx += NTHREADS) wout_s[idx] = p.W_out[idx];
    if (tid < NYO) bout_s[tid] = p.b_out[tid];
    float blat = p.b_lat[tx];

    // prefetch + commit rnn2out level 0 into buffer 0 (cols 0..63; sfc head reads 64..127 — disjoint)
    float4 lr;
    lr = *(const float4*)&g_scratch[((size_t)0 * BATCH + b0 + r16) * NH + q16 * 4];
    *(float4*)&xhb[0][r16 * KDIM + q16 * 4] = lr;
    __syncthreads();

    // ---------------- latent + out heads per level ----------------
    for (int l = 0; l < LEV; l++) {
        const float* cur = xhb[l & 1];
        float* nxt = xhb[(l + 1) & 1];
        if (l + 1 < LEV)
            lr = *(const float4*)&g_scratch[((size_t)(l + 1) * BATCH + b0 + r16) * NH + q16 * 4];

        unsigned long long accL[4];
#pragma unroll
        for (int u = 0; u < 4; u++) accL[u] = 0ull;
#pragma unroll 1
        for (int kq = 0; kq < NH / 4; kq++) {
            ulonglong2 wv = *(const ulonglong2*)&W_s[tx * KDIM + kq * 4];
#pragma unroll
            for (int u = 0; u < 4; u++) {
                ulonglong2 xv = *(const ulonglong2*)&cur[(ty * 4 + u) * KDIM + kq * 4];
                accL[u] = fma2_(xv.x, wv.x, accL[u]);
                accL[u] = fma2_(xv.y, wv.y, accL[u]);
            }
        }
#pragma unroll
        for (int u = 0; u < 4; u++) {
            int row = ty * 4 + u;
            size_t b = b0 + row;
            float v = pairsum_(accL[u]) + blat;
            lat_s[row * NH + tx] = v;
            p.out[OFF_MEM + (b * LEV + l) * NMEM + tx] = v;
        }
        if (l + 1 < LEV)
            *(float4*)&nxt[r16 * KDIM + q16 * 4] = lr;
        __syncthreads();

        // out head: (TB x 4), K = 64 over latent in lat_s
        if (tid < TB * NYO) {
            int r = tid >> 2, y = tid & 3;
            float a = bout_s[y];
            for (int mq = 0; mq < NH / 4; mq++) {
                float4 lv4 = *(const float4*)&lat_s[r * NH + mq * 4];
                a = fmaf(lv4.x, wout_s[(mq * 4 + 0) * NYO + y], a);
                a = fmaf(lv4.y, wout_s[(mq * 4 + 1) * NYO + y], a);
                a = fmaf(lv4.z, wout_s[(mq * 4 + 2) * NYO + y], a);
                a = fmaf(lv4.w, wout_s[(mq * 4 + 3) * NYO + y], a);
            }
            p.out[(size_t)(b0 + r) * (LEV * NYO) + l * NYO + y] = a;
        }
        __syncthreads();
    }
}

extern "C" void kernel_launch(void* const* d_in, const int* in_sizes, int n_in,
                              void* d_out, int out_size) {
    Params p;
    p.inputs_main = (const float*)d_in[0];
    p.inputs_aux  = (const float*)d_in[1];
    p.rnn1_mem    = (const float*)d_in[2];
    p.eps1        = (const float*)d_in[3];
    p.eps2        = (const float*)d_in[4];
    p.eps_sfc     = (const float*)d_in[5];
    p.W_sfc   = (const float*)d_in[6];  p.b_sfc   = (const float*)d_in[7];
    p.W_sfc2  = (const float*)d_in[8];  p.b_sfc2  = (const float*)d_in[9];
    p.W_toa   = (const float*)d_in[10]; p.b_toa   = (const float*)d_in[11];
    p.W_toa2  = (const float*)d_in[12]; p.b_toa2  = (const float*)d_in[13];
    p.Wx1  = (const float*)d_in[14]; p.Wh1  = (const float*)d_in[15];
    p.Wxs1 = (const float*)d_in[16]; p.Whs1 = (const float*)d_in[17];
    p.Wx2  = (const float*)d_in[18]; p.Wh2  = (const float*)d_in[19];
    p.Wxs2 = (const float*)d_in[20]; p.Whs2 = (const float*)d_in[21];
    p.W_lat    = (const float*)d_in[22]; p.b_lat    = (const float*)d_in[23];
    p.W_out    = (const float*)d_in[24]; p.b_out    = (const float*)d_in[25];
    p.W_sfcout = (const float*)d_in[26]; p.b_sfcout = (const float*)d_in[27];
    p.W_mu     = (const float*)d_in[28]; p.b_mu     = (const float*)d_in[29];
    p.W_lv     = (const float*)d_in[30]; p.b_lv     = (const float*)d_in[31];
    p.out = (float*)d_out;

    cudaFuncSetAttribute(stochastic_rnn_kernel,
                         cudaFuncAttributeMaxDynamicSharedMemorySize, SMEM_BYTES);
    stochastic_rnn_kernel<<<NBLOCKS, NTHREADS, SMEM_BYTES>>>(p);
}

// round 5
// speedup vs baseline: 1.0045x; 1.0045x over previous
#include <cuda_runtime.h>
#include <math.h>

// Problem constants
#define LEV     60
#define BATCH   4096
#define NXI     4
#define NH      64
#define NMEM    64
#define NSFC    17
#define NYO     4
#define XW1     68          // NXI + NMEM
#define KDIM    132         // unified K (rnn1: 68+64, rnn2: 64+64 zero-padded to 132)
#define NG      256         // 4*NH gate columns
#define NWCOL   320         // gates (256) + logvar (64)
#define TB      32          // batch rows per block
#define NTHREADS 256
#define NBLOCKS (BATCH / TB)   // 128

// shared layout (floats): W_s[NWCOL][KDIM] | xh0 | xh1 | lat[TB][NH] | wout | bout
#define SM_W     (NWCOL * KDIM)            // 42240
#define SM_XH    (TB * KDIM)               // 4224
#define SM_LAT   (TB * NH)                 // 2048
#define SMEM_FLOATS (SM_W + 2 * SM_XH + SM_LAT + NH * NYO + NYO)
#define SMEM_BYTES  (SMEM_FLOATS * 4)      // ~212KB < 232448 opt-in limit

// output layout: out (B,L,NYO) || out_sfc (B,3) || new_mem (B,L,NMEM)
#define OFF_OUT  0
#define OFF_SFC  (BATCH * LEV * NYO)                 // 983040
#define OFF_MEM  (OFF_SFC + BATCH * 3)               // 995328

// inter-phase scratch: rnn1out then (overwritten in place) rnn2out, [level][batch][NH]
__device__ float g_scratch[LEV * BATCH * NH];

struct Params {
    const float *inputs_main, *inputs_aux, *rnn1_mem, *eps1, *eps2, *eps_sfc;
    const float *W_sfc, *b_sfc, *W_sfc2, *b_sfc2, *W_toa, *b_toa, *W_toa2, *b_toa2;
    const float *Wx1, *Wh1, *Wxs1, *Whs1, *Wx2, *Wh2, *Wxs2, *Whs2;
    const float *W_lat, *b_lat, *W_out, *b_out, *W_sfcout, *b_sfcout;
    const float *W_mu, *b_mu, *W_lv, *b_lv;
    float *out;
};

__device__ __forceinline__ float sigmoidf_(float x) {
    return __fdividef(1.0f, 1.0f + __expf(-x));
}
__device__ __forceinline__ float tanhf_(float x) {
    float ax = fabsf(x);
    float e  = __expf(2.0f * ax);                    // overflow -> +inf -> term -> 0
    float t  = 1.0f - __fdividef(2.0f, e + 1.0f);
    return copysignf(t, x);
}

// packed fp32x2 FMA (Blackwell): d = a*b + c elementwise on {lo,hi}
__device__ __forceinline__ unsigned long long fma2_(unsigned long long a,
                                                    unsigned long long b,
                                                    unsigned long long c) {
    unsigned long long d;
    asm("fma.rn.f32x2 %0, %1, %2, %3;" : "=l"(d) : "l"(a), "l"(b), "l"(c));
    return d;
}
__device__ __forceinline__ float pairsum_(unsigned long long v) {
    float lo = __int_as_float((int)(v & 0xffffffffull));
    float hi = __int_as_float((int)(v >> 32));
    return lo + hi;
}

extern __shared__ float smem[];

__global__ __launch_bounds__(NTHREADS, 1)
void stochastic_rnn_kernel(Params p) {
    const int tid = threadIdx.x;
    const int b0  = blockIdx.x * TB;

    float* W_s  = smem;
    float* xhb[2] = { smem + SM_W, smem + SM_W + SM_XH };
    float* lat_s  = smem + SM_W + 2 * SM_XH;
    float* wout_s = lat_s + SM_LAT;
    float* bout_s = wout_s + NH * NYO;

    // thread identity: column tx (0..63), row group ty (0..3) -> rows ty*8+u (u=0..7)
    const int tx = tid & 63;
    const int ty = tid >> 6;
    // x-staging identity: row xr_r (0..31), 8-float chunk lane8 (0..7)
    const int xr_r  = tid >> 3;
    const int lane8 = tid & 7;

    float c_reg[8];

    // ---------------- load rnn1 weights (transposed; coalesced reads) ----------------
    for (int idx = tid; idx < NWCOL * KDIM; idx += NTHREADS) {
        int k = idx / NWCOL, j = idx % NWCOL;     // consecutive threads -> consecutive j
        float v;
        if (j < NG) v = (k < XW1) ? p.Wx1[k * NG + j] : p.Wh1[(k - XW1) * NG + j];
        else {
            int jj = j - NG;
            v = (k < XW1) ? p.Wxs1[k * NH + jj] : p.Whs1[(k - XW1) * NH + jj];
        }
        W_s[j * KDIM + k] = v;
    }

    // ---------------- rnn1 initial h, c from surface MLPs ----------------
#pragma unroll
    for (int u = 0; u < 8; u++) {
        int row = ty * 8 + u;
        const float* auxrow = p.inputs_aux + (size_t)(b0 + row) * NSFC;
        float ah = p.b_sfc[tx], ac = p.b_sfc2[tx];
        for (int k = 0; k < NSFC; k++) {
            float a = auxrow[k];
            ah = fmaf(a, p.W_sfc[k * NH + tx], ah);
            ac = fmaf(a, p.W_sfc2[k * NH + tx], ac);
        }
        xhb[0][row * KDIM + XW1 + tx] = tanhf_(ah);
        c_reg[u] = tanhf_(ac);
    }

    // prefetch + commit x (level 59) into buffer 0
    float mr[8]; float4 xm;
    {
        size_t rowbase = ((size_t)(b0 + xr_r) * LEV + (LEV - 1));
        *(float4*)&mr[0] = *(const float4*)&p.rnn1_mem[rowbase * NMEM + lane8 * 8];
        *(float4*)&mr[4] = *(const float4*)&p.rnn1_mem[rowbase * NMEM + lane8 * 8 + 4];
        if (lane8 == 0) xm = *(const float4*)&p.inputs_main[rowbase * NXI];
    }
    *(float4*)&xhb[0][xr_r * KDIM + NXI + lane8 * 8]     = *(const float4*)&mr[0];
    *(float4*)&xhb[0][xr_r * KDIM + NXI + lane8 * 8 + 4] = *(const float4*)&mr[4];
    if (lane8 == 0) *(float4*)&xhb[0][xr_r * KDIM] = xm;
    __syncthreads();

    // ---------------- rnn1: bottom-up, 1 sync/step, pointwise in registers ----------------
    for (int s = 0; s < LEV; s++) {
        int l = LEV - 1 - s;
        const float* cur = xhb[s & 1];
        float* nxt = xhb[(s + 1) & 1];

        // issue eps + next-x loads (latency hidden under the GEMM)
        float ge[8];
#pragma unroll
        for (int u = 0; u < 8; u++)
            ge[u] = p.eps1[((size_t)s * BATCH + b0 + ty * 8 + u) * NH + tx];
        if (s + 1 < LEV) {
            size_t rowbase = ((size_t)(b0 + xr_r) * LEV + (l - 1));
            *(float4*)&mr[0] = *(const float4*)&p.rnn1_mem[rowbase * NMEM + lane8 * 8];
            *(float4*)&mr[4] = *(const float4*)&p.rnn1_mem[rowbase * NMEM + lane8 * 8 + 4];
            if (lane8 == 0) xm = *(const float4*)&p.inputs_main[rowbase * NXI];
        }

        // fused GEMM: acc[u][c] = gate c of (row ty*8+u, col tx)
        unsigned long long acc[8][5];
#pragma unroll
        for (int u = 0; u < 8; u++)
#pragma unroll
            for (int c = 0; c < 5; c++) acc[u][c] = 0ull;
#pragma unroll 1
        for (int kq = 0; kq < KDIM / 4; kq++) {
            ulonglong2 wv[5];
#pragma unroll
            for (int c = 0; c < 5; c++)
                wv[c] = *(const ulonglong2*)&W_s[(c * 64 + tx) * KDIM + kq * 4];
#pragma unroll
            for (int u = 0; u < 8; u++) {
                ulonglong2 xv = *(const ulonglong2*)&cur[(ty * 8 + u) * KDIM + kq * 4];
#pragma unroll
                for (int c = 0; c < 5; c++) {
                    acc[u][c] = fma2_(xv.x, wv[c].x, acc[u][c]);
                    acc[u][c] = fma2_(xv.y, wv[c].y, acc[u][c]);
                }
            }
        }

        // pointwise in registers
#pragma unroll
        for (int u = 0; u < 8; u++) {
            int row = ty * 8 + u;
            float gi = pairsum_(acc[u][0]);
            float gf = pairsum_(acc[u][1]);
            float gg = pairsum_(acc[u][2]);
            float go = pairsum_(acc[u][3]);
            float gv = pairsum_(acc[u][4]);
            float iv = sigmoidf_(gi);
            float fv = sigmoidf_(gf);
            float gt = tanhf_(gg);
            float ov = sigmoidf_(go);
            float c  = fv * c_reg[u] + iv * gt;
            c_reg[u] = c;
            float h  = ov * tanhf_(c) + ge[u] * __expf(0.5f * gv);
            nxt[row * KDIM + XW1 + tx] = h;
            g_scratch[((size_t)l * BATCH + b0 + row) * NH + tx] = h;
        }
        if (s + 1 < LEV) {
            *(float4*)&nxt[xr_r * KDIM + NXI + lane8 * 8]     = *(const float4*)&mr[0];
            *(float4*)&nxt[xr_r * KDIM + NXI + lane8 * 8 + 4] = *(const float4*)&mr[4];
            if (lane8 == 0) *(float4*)&nxt[xr_r * KDIM] = xm;
        }
        __syncthreads();
    }

    // ---------------- load rnn2 weights (K padded 128->132 with zeros) ----------------
    for (int idx = tid; idx < NWCOL * KDIM; idx += NTHREADS) {
        int k = idx / NWCOL, j = idx % NWCOL;
        float v = 0.0f;
        if (j < NG) {
            if (k < NH)            v = p.Wx2[k * NG + j];
            else if (k < 2 * NH)   v = p.Wh2[(k - NH) * NG + j];
        } else {
            int jj = j - NG;
            if (k < NH)            v = p.Wxs2[k * NH + jj];
            else if (k < 2 * NH)   v = p.Whs2[(k - NH) * NH + jj];
        }
        W_s[j * KDIM + k] = v;
    }
    // zero xh pad columns 128..131 in BOTH buffers (avoid 0*NaN)
    if (tid < 256) {
        int bsel = tid >> 7, r = (tid >> 2) & 31, kk = tid & 3;
        xhb[bsel][r * KDIM + 128 + kk] = 0.0f;
    }

    // rnn2 initial h, c from TOA MLPs (inputs_toa = aux[:,1], aux[:,6])
#pragma unroll
    for (int u = 0; u < 8; u++) {
        int row = ty * 8 + u;
        float x0 = p.inputs_aux[(size_t)(b0 + row) * NSFC + 1];
        float x1 = p.inputs_aux[(size_t)(b0 + row) * NSFC + 6];
        float ah = fmaf(x0, p.W_toa[tx],  fmaf(x1, p.W_toa[NH + tx],  p.b_toa[tx]));
        float ac = fmaf(x0, p.W_toa2[tx], fmaf(x1, p.W_toa2[NH + tx], p.b_toa2[tx]));
        xhb[0][row * KDIM + NH + tx] = tanhf_(ah);
        c_reg[u] = tanhf_(ac);
    }
    // prefetch + commit x (rnn1out level 0) into buffer 0
    float hr[8];
    *(float4*)&hr[0] = *(const float4*)&g_scratch[((size_t)0 * BATCH + b0 + xr_r) * NH + lane8 * 8];
    *(float4*)&hr[4] = *(const float4*)&g_scratch[((size_t)0 * BATCH + b0 + xr_r) * NH + lane8 * 8 + 4];
    *(float4*)&xhb[0][xr_r * KDIM + lane8 * 8]     = *(const float4*)&hr[0];
    *(float4*)&xhb[0][xr_r * KDIM + lane8 * 8 + 4] = *(const float4*)&hr[4];
    __syncthreads();

    // ---------------- rnn2: top-down; overwrite scratch in place ----------------
    for (int s = 0; s < LEV; s++) {
        const float* cur = xhb[s & 1];
        float* nxt = xhb[(s + 1) & 1];

        float ge[8];
#pragma unroll
        for (int u = 0; u < 8; u++)
            ge[u] = p.eps2[((size_t)s * BATCH + b0 + ty * 8 + u) * NH + tx];
        if (s + 1 < LEV) {
            const float* sp = g_scratch + ((size_t)(s + 1) * BATCH + b0 + xr_r) * NH + lane8 * 8;
            *(float4*)&hr[0] = *(const float4*)(sp);
            *(float4*)&hr[4] = *(const float4*)(sp + 4);
        }

        unsigned long long acc[8][5];
#pragma unroll
        for (int u = 0; u < 8; u++)
#pragma unroll
            for (int c = 0; c < 5; c++) acc[u][c] = 0ull;
#pragma unroll 1
        for (int kq = 0; kq < KDIM / 4; kq++) {
            ulonglong2 wv[5];
#pragma unroll
            for (int c = 0; c < 5; c++)
                wv[c] = *(const ulonglong2*)&W_s[(c * 64 + tx) * KDIM + kq * 4];
#pragma unroll
            for (int u = 0; u < 8; u++) {
                ulonglong2 xv = *(const ulonglong2*)&cur[(ty * 8 + u) * KDIM + kq * 4];
#pragma unroll
                for (int c = 0; c < 5; c++) {
                    acc[u][c] = fma2_(xv.x, wv[c].x, acc[u][c]);
                    acc[u][c] = fma2_(xv.y, wv[c].y, acc[u][c]);
                }
            }
        }

#pragma unroll
        for (int u = 0; u < 8; u++) {
            int row = ty * 8 + u;
            float gi = pairsum_(acc[u][0]);
            float gf = pairsum_(acc[u][1]);
            float gg = pairsum_(acc[u][2]);
            float go = pairsum_(acc[u][3]);
            float gv = pairsum_(acc[u][4]);
            float iv = sigmoidf_(gi);
            float fv = sigmoidf_(gf);
            float gt = tanhf_(gg);
            float ov = sigmoidf_(go);
            float c  = fv * c_reg[u] + iv * gt;
            c_reg[u] = c;
            float h  = ov * tanhf_(c) + ge[u] * __expf(0.5f * gv);
            nxt[row * KDIM + NH + tx] = h;
            g_scratch[((size_t)s * BATCH + b0 + row) * NH + tx] = h;
        }
        if (s + 1 < LEV) {
            *(float4*)&nxt[xr_r * KDIM + lane8 * 8]     = *(const float4*)&hr[0];
            *(float4*)&nxt[xr_r * KDIM + lane8 * 8 + 4] = *(const float4*)&hr[4];
        }
        __syncthreads();
    }

    float* hlast = xhb[0];   // h of step 59 landed in buffer (59+1)&1 = 0

    // ---------------- surface heads from last hidden (cols 64..127 of hlast) ----------------
    if (tid < TB) {
        int r = tid;
        size_t b = b0 + r;
        float rad = p.b_sfcout[0];
        float mu0 = p.b_mu[0], mu1 = p.b_mu[1];
        float lv0 = p.b_lv[0], lv1 = p.b_lv[1];
        for (int k = 0; k < NH; k++) {
            float h = hlast[r * KDIM + NH + k];
            rad = fmaf(h, p.W_sfcout[k], rad);
            mu0 = fmaf(h, p.W_mu[k * 2 + 0], mu0);
            mu1 = fmaf(h, p.W_mu[k * 2 + 1], mu1);
            lv0 = fmaf(h, p.W_lv[k * 2 + 0], lv0);
            lv1 = fmaf(h, p.W_lv[k * 2 + 1], lv1);
        }
        float e0 = p.eps_sfc[b * 2 + 0], e1 = p.eps_sfc[b * 2 + 1];
        p.out[OFF_SFC + b * 3 + 0] = mu0 + e0 * __expf(0.5f * lv0);
        p.out[OFF_SFC + b * 3 + 1] = mu1 + e1 * __expf(0.5f * lv1);
        p.out[OFF_SFC + b * 3 + 2] = rad;
    }

    // ---------------- load W_lat (transposed) + W_out/b_out ----------------
    for (int idx = tid; idx < NH * NH; idx += NTHREADS) {
        int k = idx >> 6, m = idx & 63;
        W_s[m * KDIM + k] = p.W_lat[idx];
    }
    for (int idx = tid; idx < NH * NYO; idx += NTHREADS) wout_s[idx] = p.W_out[idx];
    if (tid < NYO) bout_s[tid] = p.b_out[tid];
    float blat = p.b_lat[tx];

    // prefetch + commit rnn2out level 0 into buffer 0 (cols 0..63; sfc head reads 64..127 — disjoint)
    float lr[8];
    *(float4*)&lr[0] = *(const float4*)&g_scratch[((size_t)0 * BATCH + b0 + xr_r) * NH + lane8 * 8];
    *(float4*)&lr[4] = *(const float4*)&g_scratch[((size_t)0 * BATCH + b0 + xr_r) * NH + lane8 * 8 + 4];
    *(float4*)&xhb[0][xr_r * KDIM + lane8 * 8]     = *(const float4*)&lr[0];
    *(float4*)&xhb[0][xr_r * KDIM + lane8 * 8 + 4] = *(const float4*)&lr[4];
    __syncthreads();

    // ---------------- latent + out heads per level ----------------
    for (int l = 0; l < LEV; l++) {
        const float* cur = xhb[l & 1];
        float* nxt = xhb[(l + 1) & 1];
        if (l + 1 < LEV) {
            const float* sp = g_scratch + ((size_t)(l + 1) * BATCH + b0 + xr_r) * NH + lane8 * 8;
            *(float4*)&lr[0] = *(const float4*)(sp);
            *(float4*)&lr[4] = *(const float4*)(sp + 4);
        }

        unsigned long long accL[8];
#pragma unroll
        for (int u = 0; u < 8; u++) accL[u] = 0ull;
#pragma unroll 1
        for (int kq = 0; kq < NH / 4; kq++) {
            ulonglong2 wv = *(const ulonglong2*)&W_s[tx * KDIM + kq * 4];
#pragma unroll
            for (int u = 0; u < 8; u++) {
                ulonglong2 xv = *(const ulonglong2*)&cur[(ty * 8 + u) * KDIM + kq * 4];
                accL[u] = fma2_(xv.x, wv.x, accL[u]);
                accL[u] = fma2_(xv.y, wv.y, accL[u]);
            }
        }
#pragma unroll
        for (int u = 0; u < 8; u++) {
            int row = ty * 8 + u;
            size_t b = b0 + row;
            float v = pairsum_(accL[u]) + blat;
            lat_s[row * NH + tx] = v;
            p.out[OFF_MEM + (b * LEV + l) * NMEM + tx] = v;
        }
        if (l + 1 < LEV) {
            *(float4*)&nxt[xr_r * KDIM + lane8 * 8]     = *(const float4*)&lr[0];
            *(float4*)&nxt[xr_r * KDIM + lane8 * 8 + 4] = *(const float4*)&lr[4];
        }
        __syncthreads();

        // out head: (TB x 4), K = 64 over latent in lat_s
        if (tid < TB * NYO) {
            int r = tid >> 2, y = tid & 3;
            float a = bout_s[y];
            for (int mq = 0; mq < NH / 4; mq++) {
                float4 lv4 = *(const float4*)&lat_s[r * NH + mq * 4];
                a = fmaf(lv4.x, wout_s[(mq * 4 + 0) * NYO + y], a);
                a = fmaf(lv4.y, wout_s[(mq * 4 + 1) * NYO + y], a);
                a = fmaf(lv4.z, wout_s[(mq * 4 + 2) * NYO + y], a);
                a = fmaf(lv4.w, wout_s[(mq * 4 + 3) * NYO + y], a);
            }
            p.out[(size_t)(b0 + r) * (LEV * NYO) + l * NYO + y] = a;
        }
        __syncthreads();
    }
}

extern "C" void kernel_launch(void* const* d_in, const int* in_sizes, int n_in,
                              void* d_out, int out_size) {
    Params p;
    p.inputs_main = (const float*)d_in[0];
    p.inputs_aux  = (const float*)d_in[1];
    p.rnn1_mem    = (const float*)d_in[2];
    p.eps1        = (const float*)d_in[3];
    p.eps2        = (const float*)d_in[4];
    p.eps_sfc     = (const float*)d_in[5];
    p.W_sfc   = (const float*)d_in[6];  p.b_sfc   = (const float*)d_in[7];
    p.W_sfc2  = (const float*)d_in[8];  p.b_sfc2  = (const float*)d_in[9];
    p.W_toa   = (const float*)d_in[10]; p.b_toa   = (const float*)d_in[11];
    p.W_toa2  = (const float*)d_in[12]; p.b_toa2  = (const float*)d_in[13];
    p.Wx1  = (const float*)d_in[14]; p.Wh1  = (const float*)d_in[15];
    p.Wxs1 = (const float*)d_in[16]; p.Whs1 = (const float*)d_in[17];
    p.Wx2  = (const float*)d_in[18]; p.Wh2  = (const float*)d_in[19];
    p.Wxs2 = (const float*)d_in[20]; p.Whs2 = (const float*)d_in[21];
    p.W_lat    = (const float*)d_in[22]; p.b_lat    = (const float*)d_in[23];
    p.W_out    = (const float*)d_in[24]; p.b_out    = (const float*)d_in[25];
    p.W_sfcout = (const float*)d_in[26]; p.b_sfcout = (const float*)d_in[27];
    p.W_mu     = (const float*)d_in[28]; p.b_mu     = (const float*)d_in[29];
    p.W_lv     = (const float*)d_in[30]; p.b_lv     = (const float*)d_in[31];
    p.out = (float*)d_out;

    cudaFuncSetAttribute(stochastic_rnn_kernel,
                         cudaFuncAttributeMaxDynamicSharedMemorySize, SMEM_BYTES);
    stochastic_rnn_kernel<<<NBLOCKS, NTHREADS, SMEM_BYTES>>>(p);
}

// round 6
// speedup vs baseline: 1.2175x; 1.2120x over previous
#include <cuda_runtime.h>
#include <math.h>

// Problem constants
#define LEV     60
#define BATCH   4096
#define NXI     4
#define NH      64
#define NMEM    64
#define NSFC    17
#define NYO     4
#define XW1     68          // NXI + NMEM
#define KDIM    132         // unified K (rnn1: 68+64, rnn2: 64+64 zero-padded to 132)
#define NG      256         // 4*NH gate columns
#define NWCOL   320         // gates (256) + logvar (64)
#define TB      32          // batch rows per block
#define NTHREADS 256
#define NBLOCKS (BATCH / TB)   // 128

// shared layout (floats): W_s[NWCOL][KDIM] | xh[TB][KDIM] | gacc[TB][NWCOL]
#define SM_W     (NWCOL * KDIM)            // 42240
#define SM_XH    (TB * KDIM)               // 4224
#define SM_GACC  (TB * NWCOL)              // 10240
#define SMEM_FLOATS (SM_W + SM_XH + SM_GACC)
#define SMEM_BYTES  (SMEM_FLOATS * 4)      // 226816 < 232448 opt-in limit

// output layout: out (B,L,NYO) || out_sfc (B,3) || new_mem (B,L,NMEM)
#define OFF_OUT  0
#define OFF_SFC  (BATCH * LEV * NYO)                 // 983040
#define OFF_MEM  (OFF_SFC + BATCH * 3)               // 995328

// inter-phase scratch: rnn1out then (overwritten in place) rnn2out, [level][batch][NH]
__device__ float g_scratch[LEV * BATCH * NH];

struct Params {
    const float *inputs_main, *inputs_aux, *rnn1_mem, *eps1, *eps2, *eps_sfc;
    const float *W_sfc, *b_sfc, *W_sfc2, *b_sfc2, *W_toa, *b_toa, *W_toa2, *b_toa2;
    const float *Wx1, *Wh1, *Wxs1, *Whs1, *Wx2, *Wh2, *Wxs2, *Whs2;
    const float *W_lat, *b_lat, *W_out, *b_out, *W_sfcout, *b_sfcout;
    const float *W_mu, *b_mu, *W_lv, *b_lv;
    float *out;
};

__device__ __forceinline__ float sigmoidf_(float x) {
    return __fdividef(1.0f, 1.0f + __expf(-x));
}
__device__ __forceinline__ float tanhf_(float x) {
    float ax = fabsf(x);
    float e  = __expf(2.0f * ax);                    // overflow -> +inf -> term -> 0
    float t  = 1.0f - __fdividef(2.0f, e + 1.0f);
    return copysignf(t, x);
}

// packed fp32x2 FMA (Blackwell): d = a*b + c elementwise on {lo,hi}
__device__ __forceinline__ unsigned long long fma2_(unsigned long long a,
                                                    unsigned long long b,
                                                    unsigned long long c) {
    unsigned long long d;
    asm("fma.rn.f32x2 %0, %1, %2, %3;" : "=l"(d) : "l"(a), "l"(b), "l"(c));
    return d;
}
__device__ __forceinline__ float pairsum_(unsigned long long v) {
    float lo = __int_as_float((int)(v & 0xffffffffull));
    float hi = __int_as_float((int)(v >> 32));
    return lo + hi;
}

// Fused GEMM: gacc[r][j] = sum_k xh[r][k] * W_s[j][k], r<TB, j<NWCOL, K=KDIM.
// thread (tx = tid&63, ty = tid>>6) owns cols {c*64+tx} (c=0..4) x rows {ty*8+u} (u=0..7).
// K packed in pairs via fma.rn.f32x2; unroll 2 so ptxas pipelines LDS across iterations.
__device__ __forceinline__ void gemm_step(const float* __restrict__ W_s,
                                          const float* __restrict__ xh,
                                          float* __restrict__ gacc,
                                          int tx, int ty) {
    unsigned long long acc[8][5];
#pragma unroll
    for (int u = 0; u < 8; u++)
#pragma unroll
        for (int c = 0; c < 5; c++) acc[u][c] = 0ull;

#pragma unroll 2
    for (int kq = 0; kq < KDIM / 4; kq++) {
        ulonglong2 wv[5];
#pragma unroll
        for (int c = 0; c < 5; c++)
            wv[c] = *(const ulonglong2*)&W_s[(c * 64 + tx) * KDIM + kq * 4];
#pragma unroll
        for (int u = 0; u < 8; u++) {
            ulonglong2 xv = *(const ulonglong2*)&xh[(ty * 8 + u) * KDIM + kq * 4];
#pragma unroll
            for (int c = 0; c < 5; c++) {
                acc[u][c] = fma2_(xv.x, wv[c].x, acc[u][c]);
                acc[u][c] = fma2_(xv.y, wv[c].y, acc[u][c]);
            }
        }
    }
#pragma unroll
    for (int u = 0; u < 8; u++)
#pragma unroll
        for (int c = 0; c < 5; c++)
            gacc[(ty * 8 + u) * NWCOL + c * 64 + tx] = pairsum_(acc[u][c]);
}

// LSTM pointwise for thread's 8 elems (row pr, cols pj0..pj0+7). c kept in regs.
// eps loaded here (after GEMM) — its latency hides under the gate math preamble.
__device__ __forceinline__ void pointwise_step(float* __restrict__ xh,
                                               const float* __restrict__ gacc,
                                               float* __restrict__ c_reg,
                                               int pr, int pj0, int hoff,
                                               const float* __restrict__ eps_ptr,
                                               float* __restrict__ hout_ptr) {
    float ge[8];
    *(float4*)&ge[0] = *(const float4*)(eps_ptr);
    *(float4*)&ge[4] = *(const float4*)(eps_ptr + 4);

    const float* g = gacc + pr * NWCOL + pj0;
    float gi[8], gf[8], gg[8], go[8], gv[8];
    *(float4*)&gi[0] = *(const float4*)(g);        *(float4*)&gi[4] = *(const float4*)(g + 4);
    *(float4*)&gf[0] = *(const float4*)(g + 64);   *(float4*)&gf[4] = *(const float4*)(g + 68);
    *(float4*)&gg[0] = *(const float4*)(g + 128);  *(float4*)&gg[4] = *(const float4*)(g + 132);
    *(float4*)&go[0] = *(const float4*)(g + 192);  *(float4*)&go[4] = *(const float4*)(g + 196);
    *(float4*)&gv[0] = *(const float4*)(g + 256);  *(float4*)&gv[4] = *(const float4*)(g + 260);

    float hs[8];
#pragma unroll
    for (int u = 0; u < 8; u++) {
        float iv = sigmoidf_(gi[u]);
        float fv = sigmoidf_(gf[u]);
        float gvv = tanhf_(gg[u]);
        float ov = sigmoidf_(go[u]);
        float c  = fv * c_reg[u] + iv * gvv;
        c_reg[u] = c;
        float h  = ov * tanhf_(c) + ge[u] * __expf(0.5f * gv[u]);
        xh[pr * KDIM + hoff + pj0 + u] = h;
        hs[u] = h;
    }
    *(float4*)(hout_ptr)     = *(const float4*)&hs[0];
    *(float4*)(hout_ptr + 4) = *(const float4*)&hs[4];
}

extern __shared__ float smem[];

__global__ __launch_bounds__(NTHREADS, 1)
void stochastic_rnn_kernel(Params p) {
    const int tid = threadIdx.x;
    const int b0  = blockIdx.x * TB;

    float* W_s  = smem;
    float* xh   = smem + SM_W;
    float* gacc = xh + SM_XH;

    // pointwise identity: (row pr, cols pj0..pj0+7)
    const int pr  = tid >> 3;
    const int pj0 = (tid & 7) * 8;
    // gemm identity
    const int tx = tid & 63;
    const int ty = tid >> 6;
    // x-prefetch identity: row xr_r, 8-float chunk lane8
    const int xr_r   = tid >> 3;
    const int lane8  = tid & 7;

    float c_reg[8];

    // ---------------- load rnn1 weights (transposed, fused) ----------------
    for (int idx = tid; idx < NWCOL * KDIM; idx += NTHREADS) {
        int j = idx / KDIM, k = idx % KDIM;
        float v;
        if (j < NG) v = (k < XW1) ? p.Wx1[k * NG + j] : p.Wh1[(k - XW1) * NG + j];
        else {
            int jj = j - NG;
            v = (k < XW1) ? p.Wxs1[k * NH + jj] : p.Whs1[(k - XW1) * NH + jj];
        }
        W_s[idx] = v;
    }

    // ---------------- rnn1 initial h, c from surface MLPs ----------------
    {
        const float* auxrow = p.inputs_aux + (size_t)(b0 + pr) * NSFC;
#pragma unroll
        for (int u = 0; u < 8; u++) {
            int j = pj0 + u;
            float ah = p.b_sfc[j], ac = p.b_sfc2[j];
            for (int k = 0; k < NSFC; k++) {
                float a = auxrow[k];
                ah = fmaf(a, p.W_sfc[k * NH + j], ah);
                ac = fmaf(a, p.W_sfc2[k * NH + j], ac);
            }
            xh[pr * KDIM + XW1 + j] = tanhf_(ah);
            c_reg[u] = tanhf_(ac);
        }
    }
    __syncthreads();

    // ---------------- rnn1: bottom-up over levels, x prefetch ----------------
    float mr[8];            // prefetched rnn1_mem chunk
    float xm[4];            // prefetched inputs_main chunk (lane8==0 only)
    {
        int l0 = LEV - 1;
        size_t rowbase = ((size_t)(b0 + xr_r) * LEV + l0);
        *(float4*)&mr[0] = *(const float4*)&p.rnn1_mem[rowbase * NMEM + lane8 * 8];
        *(float4*)&mr[4] = *(const float4*)&p.rnn1_mem[rowbase * NMEM + lane8 * 8 + 4];
        if (lane8 == 0)
            *(float4*)&xm[0] = *(const float4*)&p.inputs_main[rowbase * NXI];
    }

    for (int s = 0; s < LEV; s++) {
        int l = LEV - 1 - s;
        // commit prefetched x into xh
        *(float4*)&xh[xr_r * KDIM + NXI + lane8 * 8]     = *(const float4*)&mr[0];
        *(float4*)&xh[xr_r * KDIM + NXI + lane8 * 8 + 4] = *(const float4*)&mr[4];
        if (lane8 == 0)
            *(float4*)&xh[xr_r * KDIM] = *(const float4*)&xm[0];
        __syncthreads();

        // issue next-step x loads (latency hidden by GEMM)
        if (s + 1 < LEV) {
            int ln = l - 1;
            size_t rowbase = ((size_t)(b0 + xr_r) * LEV + ln);
            *(float4*)&mr[0] = *(const float4*)&p.rnn1_mem[rowbase * NMEM + lane8 * 8];
            *(float4*)&mr[4] = *(const float4*)&p.rnn1_mem[rowbase * NMEM + lane8 * 8 + 4];
            if (lane8 == 0)
                *(float4*)&xm[0] = *(const float4*)&p.inputs_main[rowbase * NXI];
        }

        gemm_step(W_s, xh, gacc, tx, ty);
        __syncthreads();
        pointwise_step(xh, gacc, c_reg, pr, pj0, XW1,
                       p.eps1 + ((size_t)s * BATCH + b0 + pr) * NH + pj0,
                       g_scratch + ((size_t)l * BATCH + b0 + pr) * NH + pj0);
        __syncthreads();
    }

    // ---------------- load rnn2 weights (K padded 128->132 with zeros) ----------------
    for (int idx = tid; idx < NWCOL * KDIM; idx += NTHREADS) {
        int j = idx / KDIM, k = idx % KDIM;
        float v = 0.0f;
        if (j < NG) {
            if (k < NH)            v = p.Wx2[k * NG + j];
            else if (k < 2 * NH)   v = p.Wh2[(k - NH) * NG + j];
        } else {
            int jj = j - NG;
            if (k < NH)            v = p.Wxs2[k * NH + jj];
            else if (k < 2 * NH)   v = p.Whs2[(k - NH) * NH + jj];
        }
        W_s[idx] = v;
    }
    // zero xh pad columns 128..131
    for (int idx = tid; idx < TB * 4; idx += NTHREADS)
        xh[(idx >> 2) * KDIM + 128 + (idx & 3)] = 0.0f;

    // rnn2 initial h, c from TOA MLPs (inputs_toa = aux[:,1], aux[:,6])
    {
        float x0 = p.inputs_aux[(size_t)(b0 + pr) * NSFC + 1];
        float x1 = p.inputs_aux[(size_t)(b0 + pr) * NSFC + 6];
#pragma unroll
        for (int u = 0; u < 8; u++) {
            int j = pj0 + u;
            float ah = fmaf(x0, p.W_toa[j],  fmaf(x1, p.W_toa[NH + j],  p.b_toa[j]));
            float ac = fmaf(x0, p.W_toa2[j], fmaf(x1, p.W_toa2[NH + j], p.b_toa2[j]));
            xh[pr * KDIM + NH + j] = tanhf_(ah);
            c_reg[u] = tanhf_(ac);
        }
    }
    __syncthreads();

    // ---------------- rnn2: top-down over levels; overwrite scratch in place ----------------
    float hr[8];
    {
        const float* sp = g_scratch + ((size_t)0 * BATCH + b0 + pr) * NH + pj0;
        *(float4*)&hr[0] = *(const float4*)(sp);
        *(float4*)&hr[4] = *(const float4*)(sp + 4);
    }
    for (int s = 0; s < LEV; s++) {
        *(float4*)&xh[pr * KDIM + pj0]     = *(const float4*)&hr[0];
        *(float4*)&xh[pr * KDIM + pj0 + 4] = *(const float4*)&hr[4];
        __syncthreads();

        if (s + 1 < LEV) {
            const float* sp = g_scratch + ((size_t)(s + 1) * BATCH + b0 + pr) * NH + pj0;
            *(float4*)&hr[0] = *(const float4*)(sp);
            *(float4*)&hr[4] = *(const float4*)(sp + 4);
        }

        gemm_step(W_s, xh, gacc, tx, ty);
        __syncthreads();
        pointwise_step(xh, gacc, c_reg, pr, pj0, NH,
                       p.eps2 + ((size_t)s * BATCH + b0 + pr) * NH + pj0,
                       g_scratch + ((size_t)s * BATCH + b0 + pr) * NH + pj0);
        __syncthreads();
    }

    // ---------------- surface heads from last hidden (in xh cols 64..127) ----------------
    if (tid < TB) {
        int r = tid;
        size_t b = b0 + r;
        float rad = p.b_sfcout[0];
        float mu0 = p.b_mu[0], mu1 = p.b_mu[1];
        float lv0 = p.b_lv[0], lv1 = p.b_lv[1];
        for (int k = 0; k < NH; k++) {
            float h = xh[r * KDIM + NH + k];
            rad = fmaf(h, p.W_sfcout[k], rad);
            mu0 = fmaf(h, p.W_mu[k * 2 + 0], mu0);
            mu1 = fmaf(h, p.W_mu[k * 2 + 1], mu1);
            lv0 = fmaf(h, p.W_lv[k * 2 + 0], lv0);
            lv1 = fmaf(h, p.W_lv[k * 2 + 1], lv1);
        }
        float e0 = p.eps_sfc[b * 2 + 0], e1 = p.eps_sfc[b * 2 + 1];
        p.out[OFF_SFC + b * 3 + 0] = mu0 + e0 * __expf(0.5f * lv0);
        p.out[OFF_SFC + b * 3 + 1] = mu1 + e1 * __expf(0.5f * lv1);
        p.out[OFF_SFC + b * 3 + 2] = rad;
    }
}

// ================= kernel 2: latent + out heads, fully level-parallel =================
__global__ __launch_bounds__(256, 2)
void latent_kernel(const float* __restrict__ W_lat, const float* __restrict__ b_lat,
                   const float* __restrict__ W_out, const float* __restrict__ b_out,
                   float* __restrict__ out) {
    __shared__ float Wl[NH * 68];          // transposed, padded stride 68
    __shared__ float wout[NH * NYO + NYO];
    __shared__ float xt[TB * 68];
    __shared__ float lat[TB * 68];

    const int l  = blockIdx.y;
    const int b0 = blockIdx.x * TB;
    const int tid = threadIdx.x;
    const int tx = tid & 63;
    const int ty = tid >> 6;

    for (int i = tid; i < NH * NH; i += 256) {
        int k = i >> 6, m = i & 63;
        Wl[m * 68 + k] = W_lat[i];
    }
    for (int i = tid; i < NH * NYO; i += 256) wout[i] = W_out[i];
    if (tid < NYO) wout[NH * NYO + tid] = b_out[tid];

    const float* src = g_scratch + ((size_t)l * BATCH + b0) * NH;
    for (int i = tid; i < TB * NH / 4; i += 256) {
        int r = i >> 4, q = i & 15;
        *(float4*)&xt[r * 68 + q * 4] = *(const float4*)&src[r * NH + q * 4];
    }
    __syncthreads();

    float accL[8];
    float bl = b_lat[tx];
#pragma unroll
    for (int u = 0; u < 8; u++) accL[u] = bl;
    for (int k = 0; k < NH; k += 4) {
        float4 wv = *(const float4*)&Wl[tx * 68 + k];
#pragma unroll
        for (int u = 0; u < 8; u++) {
            float4 xv = *(const float4*)&xt[(ty * 8 + u) * 68 + k];
            accL[u] = fmaf(xv.x, wv.x, accL[u]);
            accL[u] = fmaf(xv.y, wv.y, accL[u]);
            accL[u] = fmaf(xv.z, wv.z, accL[u]);
            accL[u] = fmaf(xv.w, wv.w, accL[u]);
        }
    }
#pragma unroll
    for (int u = 0; u < 8; u++) {
        int r = ty * 8 + u;
        size_t b = b0 + r;
        lat[r * 68 + tx] = accL[u];
        out[OFF_MEM + (b * LEV + l) * NMEM + tx] = accL[u];
    }
    __syncthreads();

    if (tid < TB * NYO) {
        int r = tid >> 2, y = tid & 3;
        float a = wout[NH * NYO + y];
        for (int m = 0; m < NH; m += 4) {
            a = fmaf(lat[r * 68 + m + 0], wout[(m + 0) * NYO + y], a);
            a = fmaf(lat[r * 68 + m + 1], wout[(m + 1) * NYO + y], a);
            a = fmaf(lat[r * 68 + m + 2], wout[(m + 2) * NYO + y], a);
            a = fmaf(lat[r * 68 + m + 3], wout[(m + 3) * NYO + y], a);
        }
        out[(size_t)(b0 + r) * (LEV * NYO) + l * NYO + y] = a;
    }
}

extern "C" void kernel_launch(void* const* d_in, const int* in_sizes, int n_in,
                              void* d_out, int out_size) {
    Params p;
    p.inputs_main = (const float*)d_in[0];
    p.inputs_aux  = (const float*)d_in[1];
    p.rnn1_mem    = (const float*)d_in[2];
    p.eps1        = (const float*)d_in[3];
    p.eps2        = (const float*)d_in[4];
    p.eps_sfc     = (const float*)d_in[5];
    p.W_sfc   = (const float*)d_in[6];  p.b_sfc   = (const float*)d_in[7];
    p.W_sfc2  = (const float*)d_in[8];  p.b_sfc2  = (const float*)d_in[9];
    p.W_toa   = (const float*)d_in[10]; p.b_toa   = (const float*)d_in[11];
    p.W_toa2  = (const float*)d_in[12]; p.b_toa2  = (const float*)d_in[13];
    p.Wx1  = (const float*)d_in[14]; p.Wh1  = (const float*)d_in[15];
    p.Wxs1 = (const float*)d_in[16]; p.Whs1 = (const float*)d_in[17];
    p.Wx2  = (const float*)d_in[18]; p.Wh2  = (const float*)d_in[19];
    p.Wxs2 = (const float*)d_in[20]; p.Whs2 = (const float*)d_in[21];
    p.W_lat    = (const float*)d_in[22]; p.b_lat    = (const float*)d_in[23];
    p.W_out    = (const float*)d_in[24]; p.b_out    = (const float*)d_in[25];
    p.W_sfcout = (const float*)d_in[26]; p.b_sfcout = (const float*)d_in[27];
    p.W_mu     = (const float*)d_in[28]; p.b_mu     = (const float*)d_in[29];
    p.W_lv     = (const float*)d_in[30]; p.b_lv     = (const float*)d_in[31];
    p.out = (float*)d_out;

    cudaFuncSetAttribute(stochastic_rnn_kernel,
                         cudaFuncAttributeMaxDynamicSharedMemorySize, SMEM_BYTES);
    stochastic_rnn_kernel<<<NBLOCKS, NTHREADS, SMEM_BYTES>>>(p);

    dim3 g2(NBLOCKS, LEV);
    latent_kernel<<<g2, 256>>>(p.W_lat, p.b_lat, p.W_out, p.b_out, p.out);
}